// round 11
// baseline (speedup 1.0000x reference)
#include <cuda_runtime.h>
#include <cuda_fp16.h>
#include <cstdint>

// CMPModel density matrix via fp16 mma.sync m16n8k16 (f32 accum), sm_103.
// V=50000, D=256, S=128, B=64.
//
// R[k,d]=word_emb[q[k],d], I[k,d]=cmp_emb[q[k],d]*pos[k]
//   real[d,e] = sum_k w[k]( R[k,d]R[k,e] + I[k,d]I[k,e] )
//   imag[d,e] = sum_k w[k]( I[k,d]R[k,e] - R[k,d]I[k,e] )
//
// LSU-floor analysis: gather LDG count is the binder (1.82 cyc/LDG/SM).
// So: CTA = (batch, d-half) -> 128 CTAs (0.86 waves instead of 2), each
// loads the FULL 256-feat range ONCE as unscaled fp16 R/I tiles (A and B
// fragments come from the same tiles; w applied on the fly to B fragments
// with mul.f16x2 from a half2 w-pair table).  Two e-half output passes.
// Fragments via ldmatrix.x4.trans ([k][256feat] tiles, 512B rows,
// chunk^(k&7) swizzle).  Imag minus sign: negate aR fragment (XOR).

#define D_DIM 256
#define S_LEN 128
#define B_DIM 64

#define R_OFF  0
#define I_OFF  65536                        // 128k x 256feat x 2B = 64KB each
#define W2_OFF 131072                       // 64 x half2 w pairs
#define SMEM_BYTES (131072 + 256)

__device__ __forceinline__ void ldmx4t(uint32_t* r, uint32_t addr) {
    asm("ldmatrix.sync.aligned.m8n8.x4.trans.shared.b16 {%0,%1,%2,%3}, [%4];"
        : "=r"(r[0]), "=r"(r[1]), "=r"(r[2]), "=r"(r[3]) : "r"(addr));
}

__device__ __forceinline__ void mma16(float* c, const uint32_t* a,
                                      const uint32_t* b) {
    asm("mma.sync.aligned.m16n8k16.row.col.f32.f16.f16.f32 "
        "{%0,%1,%2,%3}, {%4,%5,%6,%7}, {%8,%9}, {%0,%1,%2,%3};"
        : "+f"(c[0]), "+f"(c[1]), "+f"(c[2]), "+f"(c[3])
        : "r"(a[0]), "r"(a[1]), "r"(a[2]), "r"(a[3]), "r"(b[0]), "r"(b[1]));
}

__device__ __forceinline__ uint32_t h2(float x, float y) {
    __half2 h = __halves2half2(__float2half_rn(x), __float2half_rn(y));
    return *reinterpret_cast<uint32_t*>(&h);
}

__device__ __forceinline__ uint32_t hmul2u(uint32_t a, uint32_t b) {
    uint32_t d;
    asm("mul.f16x2 %0, %1, %2;" : "=r"(d) : "r"(a), "r"(b));
    return d;
}

__global__ void __launch_bounds__(512, 1)
cmp_fp16c_kernel(const int*   __restrict__ questions,
                 const float* __restrict__ qpos,
                 const float* __restrict__ wemb,
                 const float* __restrict__ cemb,
                 const float* __restrict__ wq,
                 float*       __restrict__ out)
{
    extern __shared__ char sm[];
    __shared__ int   sq[S_LEN];
    __shared__ float sp[S_LEN];

    const int tid  = threadIdx.x;
    const int wid  = tid >> 5;
    const int lane = tid & 31;
    const int dh   = blockIdx.x;   // d-half 0/1
    const int b    = blockIdx.y;   // batch

    const uint32_t smem_u = (uint32_t)__cvta_generic_to_shared(sm);
    uint32_t* w2s = (uint32_t*)(sm + W2_OFF);

    if (tid < S_LEN) {
        sq[tid] = questions[b * S_LEN + tid];
        sp[tid] = qpos[b * S_LEN + tid];
    }
    if (tid < 64) {
        w2s[tid] = h2(wq[2 * tid], wq[2 * tid + 1]);
    }
    __syncthreads();

    // ---- gather: full 256-feat range, unscaled R and pos-scaled I ----
    // 8192 tasks (128 k x 64 f4), 16 per thread; 2 LDG.128 + 2 STS.64 each.
#pragma unroll 4
    for (int i = 0; i < 16; ++i) {
        const int t  = tid + i * 512;
        const int k  = t >> 6;
        const int f4 = t & 63;
        const int   q  = sq[k];
        const float pp = sp[k];
        const float4 rv = *(const float4*)(wemb + (size_t)q * D_DIM + f4 * 4);
        const float4 cv = *(const float4*)(cemb + (size_t)q * D_DIM + f4 * 4);

        const uint32_t dst = smem_u +
            (uint32_t)k * 512 +
            (uint32_t)((((f4 >> 1) ^ (k & 7)) << 4) + (f4 & 1) * 8);

        uint2 vR = make_uint2(h2(rv.x, rv.y), h2(rv.z, rv.w));
        uint2 vI = make_uint2(h2(cv.x * pp, cv.y * pp),
                              h2(cv.z * pp, cv.w * pp));
        asm volatile("st.shared.v2.b32 [%0], {%1,%2};"
                     :: "r"(dst + R_OFF), "r"(vR.x), "r"(vR.y));
        asm volatile("st.shared.v2.b32 [%0], {%1,%2};"
                     :: "r"(dst + I_OFF), "r"(vI.x), "r"(vI.y));
    }
    __syncthreads();

    // ---- fragment addressing ----
    const int mr = wid >> 2;       // d block (32 rows), 0..3
    const int nc = wid & 3;        // e block (32 cols), 0..3
    const int xorv  = lane & 7;
    const int krowA = (lane & 7) | ((lane & 16) >> 1);   // A: m8-sel in bit3
    const int aCh   = (lane >> 3) & 1;
    const int krowB = (lane & 7) | (lane & 8);           // B: n8-sel in bit4
    const int bCh   = (lane >> 4) & 1;

    const uint32_t aBase = (uint32_t)krowA * 512 + (uint32_t)dh * 256 +
        (uint32_t)((((mr * 4 + aCh) ^ xorv)) << 4);
    const uint32_t bBase0 = (uint32_t)krowB * 512 +
        (uint32_t)((((nc * 4 + bCh) ^ xorv)) << 4);

    const int wsel = lane & 3;     // w2 pair sub-index

    float accRe[2][4][4];
    float accIm[2][4][4];

    float* oRe = out + (size_t)b * D_DIM * D_DIM;
    float* oIm = oRe + (size_t)B_DIM * D_DIM * D_DIM;
    const int r = lane >> 2;
    const int c = lane & 3;

#pragma unroll
    for (int et = 0; et < 2; ++et) {
#pragma unroll
        for (int i = 0; i < 2; i++)
#pragma unroll
            for (int j = 0; j < 4; j++)
#pragma unroll
                for (int q = 0; q < 4; q++) { accRe[i][j][q] = 0.f; accIm[i][j][q] = 0.f; }

        const uint32_t bBase = bBase0 + (uint32_t)et * 256;

#pragma unroll
        for (int kg = 0; kg < 8; ++kg) {
            const uint32_t kofs = (uint32_t)kg * 8192;   // 16 k-rows * 512B

            // w pair halves for this kg: reg r=0 -> lo, r=1 -> hi
            const uint32_t w2lo = w2s[kg * 8 + wsel];
            const uint32_t w2hi = w2s[kg * 8 + 4 + wsel];

            // ---- B fragments from shared R/I tiles, scaled by w ----
            uint32_t bR[8], bI[8];
#pragma unroll
            for (int ntp = 0; ntp < 2; ++ntp) {
                const uint32_t badj = bBase ^ (uint32_t)(ntp * 32);
                uint32_t tR[4], tI[4];
                ldmx4t(tR, smem_u + R_OFF + kofs + badj);
                ldmx4t(tI, smem_u + I_OFF + kofs + badj);
#pragma unroll
                for (int j = 0; j < 4; ++j) {
                    const uint32_t wsel2 = (j & 1) ? w2hi : w2lo;
                    bR[4 * ntp + j] = hmul2u(tR[j], wsel2);
                    bI[4 * ntp + j] = hmul2u(tI[j], wsel2);
                }
            }

            // ---- A fragments (unscaled) + MMAs ----
#pragma unroll
            for (int mt = 0; mt < 2; ++mt) {
                const uint32_t aadj = aBase ^ (uint32_t)(mt * 32);
                uint32_t aR[4], aI[4], aN[4];
                ldmx4t(aR, smem_u + R_OFF + kofs + aadj);
                ldmx4t(aI, smem_u + I_OFF + kofs + aadj);
#pragma unroll
                for (int j = 0; j < 4; ++j) aN[j] = aR[j] ^ 0x80008000u;

#pragma unroll
                for (int nt = 0; nt < 4; ++nt) {
                    const int bi = (nt >> 1) * 4 + (nt & 1) * 2;
                    mma16(accRe[mt][nt], aR, bR + bi);
                }
#pragma unroll
                for (int nt = 0; nt < 4; ++nt) {
                    const int bi = (nt >> 1) * 4 + (nt & 1) * 2;
                    mma16(accRe[mt][nt], aI, bI + bi);
                }
#pragma unroll
                for (int nt = 0; nt < 4; ++nt) {
                    const int bi = (nt >> 1) * 4 + (nt & 1) * 2;
                    mma16(accIm[mt][nt], aI, bR + bi);
                }
#pragma unroll
                for (int nt = 0; nt < 4; ++nt) {
                    const int bi = (nt >> 1) * 4 + (nt & 1) * 2;
                    mma16(accIm[mt][nt], aN, bI + bi);
                }
            }
        }

        // ---- epilogue for quadrant (dh, et) ----
#pragma unroll
        for (int mt = 0; mt < 2; ++mt) {
            const int d = dh * 128 + mr * 32 + mt * 16 + r;
#pragma unroll
            for (int nt = 0; nt < 4; ++nt) {
                const int e = et * 128 + nc * 32 + nt * 8 + 2 * c;
                *(float2*)(oRe + (size_t)d * D_DIM + e) =
                    make_float2(accRe[mt][nt][0], accRe[mt][nt][1]);
                *(float2*)(oRe + (size_t)(d + 8) * D_DIM + e) =
                    make_float2(accRe[mt][nt][2], accRe[mt][nt][3]);
                *(float2*)(oIm + (size_t)d * D_DIM + e) =
                    make_float2(accIm[mt][nt][0], accIm[mt][nt][1]);
                *(float2*)(oIm + (size_t)(d + 8) * D_DIM + e) =
                    make_float2(accIm[mt][nt][2], accIm[mt][nt][3]);
            }
        }
    }
}

extern "C" void kernel_launch(void* const* d_in, const int* in_sizes, int n_in,
                              void* d_out, int out_size) {
    const int*   questions = (const int*)d_in[0];
    const float* qpos      = (const float*)d_in[1];
    const float* wemb      = (const float*)d_in[2];
    const float* cemb      = (const float*)d_in[3];
    const float* wq        = (const float*)d_in[4];
    float*       out       = (float*)d_out;

    cudaFuncSetAttribute(cmp_fp16c_kernel,
                         cudaFuncAttributeMaxDynamicSharedMemorySize, SMEM_BYTES);

    dim3 grid(2 /*d-half*/, B_DIM /*batch*/);
    cmp_fp16c_kernel<<<grid, 512, SMEM_BYTES>>>(questions, qpos, wemb, cemb,
                                                wq, out);
}

// round 12
// speedup vs baseline: 1.9079x; 1.9079x over previous
#include <cuda_runtime.h>
#include <cuda_fp16.h>
#include <cstdint>

// CMPModel density matrix via fp16 mma.sync m16n8k16 (f32 accum), sm_103.
// V=50000, D=256, S=128, B=64.
//
// R[k,d]=word_emb[q[k],d], I[k,d]=cmp_emb[q[k],d]*pos[k]
//   real[d,e] = sum_k w[k]( R[k,d]R[k,e] + I[k,d]I[k,e] )
//   imag[d,e] = sum_k w[k]( I[k,d]R[k,e] - R[k,d]I[k,e] )
//
// CTA = (e-half, d-half, batch), 256 CTAs (R9 structure: L2-optimal).
// NEW: diagonal CTAs (dt==et) load only unscaled R/I tiles (HALF the LDGs)
// and form B fragments as w * fragment via mul.f16x2 (w-pair table),
// the mapping validated in round 11.  Off-diagonal CTAs = round-9 path.

#define D_DIM 256
#define S_LEN 128
#define B_DIM 64
#define KC    32

#define TILE_BYTES  8192                    // 32 k x 128 feat x 2B
#define STAGE_BYTES 32768
#define SMEM_BYTES  (2 * STAGE_BYTES)       // 64KB

#define AR_OFF 0
#define AI_OFF 8192
#define BR_OFF 16384
#define BI_OFF 24576

__device__ __forceinline__ void ldmx4t(uint32_t* r, uint32_t addr) {
    asm("ldmatrix.sync.aligned.m8n8.x4.trans.shared.b16 {%0,%1,%2,%3}, [%4];"
        : "=r"(r[0]), "=r"(r[1]), "=r"(r[2]), "=r"(r[3]) : "r"(addr));
}

__device__ __forceinline__ void mma16(float* c, const uint32_t* a,
                                      const uint32_t* b) {
    asm("mma.sync.aligned.m16n8k16.row.col.f32.f16.f16.f32 "
        "{%0,%1,%2,%3}, {%4,%5,%6,%7}, {%8,%9}, {%0,%1,%2,%3};"
        : "+f"(c[0]), "+f"(c[1]), "+f"(c[2]), "+f"(c[3])
        : "r"(a[0]), "r"(a[1]), "r"(a[2]), "r"(a[3]), "r"(b[0]), "r"(b[1]));
}

__device__ __forceinline__ uint32_t h2(float x, float y) {
    __half2 h = __halves2half2(__float2half_rn(x), __float2half_rn(y));
    return *reinterpret_cast<uint32_t*>(&h);
}

__device__ __forceinline__ uint32_t hmul2u(uint32_t a, uint32_t b) {
    uint32_t d;
    asm("mul.f16x2 %0, %1, %2;" : "=r"(d) : "r"(a), "r"(b));
    return d;
}

__global__ void __launch_bounds__(512, 1)
cmp_fp16d_kernel(const int*   __restrict__ questions,
                 const float* __restrict__ qpos,
                 const float* __restrict__ wemb,
                 const float* __restrict__ cemb,
                 const float* __restrict__ wq,
                 float*       __restrict__ out)
{
    extern __shared__ char sm[];
    __shared__ int      sq[S_LEN];
    __shared__ float    sp[S_LEN];
    __shared__ float    sw[S_LEN];
    __shared__ uint32_t w2s[S_LEN / 2];

    const int tid  = threadIdx.x;
    const int wid  = tid >> 5;
    const int lane = tid & 31;
    const int et   = blockIdx.x;
    const int dt   = blockIdx.y;
    const int b    = blockIdx.z;
    const bool diag = (et == dt);

    if (tid < S_LEN) {
        sq[tid] = questions[b * S_LEN + tid];
        sp[tid] = qpos[b * S_LEN + tid];
        sw[tid] = wq[tid];
    }
    if (tid < S_LEN / 2) {
        w2s[tid] = h2(wq[2 * tid], wq[2 * tid + 1]);
    }
    __syncthreads();

    const uint32_t smem_u = (uint32_t)__cvta_generic_to_shared(sm);

    const int mr = wid >> 2;       // d block (32 rows), 0..3
    const int nc = wid & 3;        // e block (32 cols), 0..3

    float accRe[2][4][4];
    float accIm[2][4][4];
#pragma unroll
    for (int i = 0; i < 2; i++)
#pragma unroll
        for (int j = 0; j < 4; j++)
#pragma unroll
            for (int q = 0; q < 4; q++) { accRe[i][j][q] = 0.f; accIm[i][j][q] = 0.f; }

    // ldmatrix per-lane address components
    const int xorv  = lane & 7;
    const int krowA = (lane & 7) | ((lane & 16) >> 1);   // A: m8-sel in bit3
    const int aCh   = (lane >> 3) & 1;
    const int krowB = (lane & 7) | (lane & 8);           // B: n8-sel in bit4
    const int bCh   = (lane >> 4) & 1;

    const uint32_t aBase = (uint32_t)krowA * 256 +
        (uint32_t)(((mr * 4 + aCh) ^ xorv) * 16);
    const uint32_t bBase = (uint32_t)krowB * 256 +
        (uint32_t)(((nc * 4 + bCh) ^ xorv) * 16);

    const int wsel = lane & 3;

    if (diag) {
        // ================= diagonal CTA: dt == et =================
        // gather only unscaled R/I tiles for the shared feature half.
        auto gatherD = [&](int g) {
            const uint32_t stg = smem_u + (uint32_t)(g & 1) * STAGE_BYTES;
#pragma unroll
            for (int i = 0; i < 2; ++i) {
                const int t    = tid + i * 512;         // 0..1023
                const int k    = t >> 5;                // 0..31
                const int f4   = t & 31;
                const int fofs = dt * 128 + f4 * 4;

                const int   s  = g * KC + k;
                const int   q  = sq[s];
                const float pp = sp[s];
                const float4 rv = *(const float4*)(wemb + (size_t)q * D_DIM + fofs);
                const float4 cv = *(const float4*)(cemb + (size_t)q * D_DIM + fofs);

                const uint32_t dst = stg +
                    (uint32_t)k * 256 +
                    (uint32_t)(((f4 >> 1) ^ (k & 7)) * 16 + (f4 & 1) * 8);

                uint2 vR = make_uint2(h2(rv.x, rv.y), h2(rv.z, rv.w));
                uint2 vI = make_uint2(h2(cv.x * pp, cv.y * pp),
                                      h2(cv.z * pp, cv.w * pp));
                asm volatile("st.shared.v2.b32 [%0], {%1,%2};"
                             :: "r"(dst + AR_OFF), "r"(vR.x), "r"(vR.y));
                asm volatile("st.shared.v2.b32 [%0], {%1,%2};"
                             :: "r"(dst + AI_OFF), "r"(vI.x), "r"(vI.y));
            }
        };

        gatherD(0);
        __syncthreads();

        for (int g = 0; g < 4; ++g) {
            const uint32_t stg = smem_u + (uint32_t)(g & 1) * STAGE_BYTES;
            if (g < 3) gatherD(g + 1);

#pragma unroll
            for (int kg = 0; kg < 2; ++kg) {
                const uint32_t kofs = (uint32_t)kg * 4096;
                const int wbase = g * 16 + kg * 8;
                const uint32_t w2lo = w2s[wbase + wsel];
                const uint32_t w2hi = w2s[wbase + 4 + wsel];

                // B fragments = w * (R/I fragments) from the A tiles
                uint32_t bR[8], bI[8];
#pragma unroll
                for (int ntp = 0; ntp < 2; ++ntp) {
                    const uint32_t badj = bBase ^ (uint32_t)(ntp * 32);
                    uint32_t tR[4], tI[4];
                    ldmx4t(tR, stg + AR_OFF + kofs + badj);
                    ldmx4t(tI, stg + AI_OFF + kofs + badj);
#pragma unroll
                    for (int j = 0; j < 4; ++j) {
                        const uint32_t wv = (j & 1) ? w2hi : w2lo;
                        bR[4 * ntp + j] = hmul2u(tR[j], wv);
                        bI[4 * ntp + j] = hmul2u(tI[j], wv);
                    }
                }

#pragma unroll
                for (int mt = 0; mt < 2; ++mt) {
                    const uint32_t aadj = aBase ^ (uint32_t)(mt * 32);
                    uint32_t aR[4], aI[4], aN[4];
                    ldmx4t(aR, stg + AR_OFF + kofs + aadj);
                    ldmx4t(aI, stg + AI_OFF + kofs + aadj);
#pragma unroll
                    for (int j = 0; j < 4; ++j) aN[j] = aR[j] ^ 0x80008000u;

#pragma unroll
                    for (int nt = 0; nt < 4; ++nt) {
                        const int bi = (nt >> 1) * 4 + (nt & 1) * 2;
                        mma16(accRe[mt][nt], aR, bR + bi);
                    }
#pragma unroll
                    for (int nt = 0; nt < 4; ++nt) {
                        const int bi = (nt >> 1) * 4 + (nt & 1) * 2;
                        mma16(accRe[mt][nt], aI, bI + bi);
                    }
#pragma unroll
                    for (int nt = 0; nt < 4; ++nt) {
                        const int bi = (nt >> 1) * 4 + (nt & 1) * 2;
                        mma16(accIm[mt][nt], aI, bR + bi);
                    }
#pragma unroll
                    for (int nt = 0; nt < 4; ++nt) {
                        const int bi = (nt >> 1) * 4 + (nt & 1) * 2;
                        mma16(accIm[mt][nt], aN, bI + bi);
                    }
                }
            }
            __syncthreads();
        }
    } else {
        // ================= off-diagonal CTA: round-9 path =================
        auto gather = [&](int g) {
            const uint32_t stg = smem_u + (uint32_t)(g & 1) * STAGE_BYTES;
#pragma unroll
            for (int i = 0; i < 4; ++i) {
                const int t    = tid + i * 512;
                const int half = t >> 10;
                const int k    = (t >> 5) & 31;
                const int f4   = t & 31;
                const int fofs = (half ? et : dt) * 128 + f4 * 4;

                const int   s  = g * KC + k;
                const int   q  = sq[s];
                const float pp = sp[s];
                const float4 rv = *(const float4*)(wemb + (size_t)q * D_DIM + fofs);
                const float4 cv = *(const float4*)(cemb + (size_t)q * D_DIM + fofs);

                const uint32_t dst = stg + (half ? BR_OFF : AR_OFF) +
                    (uint32_t)k * 256 +
                    (uint32_t)(((f4 >> 1) ^ (k & 7)) * 16 + (f4 & 1) * 8);

                if (half == 0) {
                    uint2 vR = make_uint2(h2(rv.x, rv.y), h2(rv.z, rv.w));
                    uint2 vI = make_uint2(h2(cv.x * pp, cv.y * pp),
                                          h2(cv.z * pp, cv.w * pp));
                    asm volatile("st.shared.v2.b32 [%0], {%1,%2};"
                                 :: "r"(dst), "r"(vR.x), "r"(vR.y));
                    asm volatile("st.shared.v2.b32 [%0], {%1,%2};"
                                 :: "r"(dst + (AI_OFF - AR_OFF)), "r"(vI.x), "r"(vI.y));
                } else {
                    const float ww = sw[s];
                    const float wp = ww * pp;
                    uint2 vR = make_uint2(h2(rv.x * ww, rv.y * ww),
                                          h2(rv.z * ww, rv.w * ww));
                    uint2 vI = make_uint2(h2(cv.x * wp, cv.y * wp),
                                          h2(cv.z * wp, cv.w * wp));
                    asm volatile("st.shared.v2.b32 [%0], {%1,%2};"
                                 :: "r"(dst), "r"(vR.x), "r"(vR.y));
                    asm volatile("st.shared.v2.b32 [%0], {%1,%2};"
                                 :: "r"(dst + (BI_OFF - BR_OFF)), "r"(vI.x), "r"(vI.y));
                }
            }
        };

        gather(0);
        __syncthreads();

        for (int g = 0; g < 4; ++g) {
            const uint32_t stg = smem_u + (uint32_t)(g & 1) * STAGE_BYTES;
            if (g < 3) gather(g + 1);

#pragma unroll
            for (int kg = 0; kg < 2; ++kg) {
                const uint32_t kofs = (uint32_t)kg * 4096;

                uint32_t bR[8], bI[8];
#pragma unroll
                for (int ntp = 0; ntp < 2; ++ntp) {
                    const uint32_t badj = bBase ^ (uint32_t)(ntp * 32);
                    ldmx4t(bR + 4 * ntp, stg + BR_OFF + kofs + badj);
                    ldmx4t(bI + 4 * ntp, stg + BI_OFF + kofs + badj);
                }

#pragma unroll
                for (int mt = 0; mt < 2; ++mt) {
                    const uint32_t aadj = aBase ^ (uint32_t)(mt * 32);
                    uint32_t aR[4], aI[4], aN[4];
                    ldmx4t(aR, stg + AR_OFF + kofs + aadj);
                    ldmx4t(aI, stg + AI_OFF + kofs + aadj);
#pragma unroll
                    for (int j = 0; j < 4; ++j) aN[j] = aR[j] ^ 0x80008000u;

#pragma unroll
                    for (int nt = 0; nt < 4; ++nt) {
                        const int bi = (nt >> 1) * 4 + (nt & 1) * 2;
                        mma16(accRe[mt][nt], aR, bR + bi);
                    }
#pragma unroll
                    for (int nt = 0; nt < 4; ++nt) {
                        const int bi = (nt >> 1) * 4 + (nt & 1) * 2;
                        mma16(accRe[mt][nt], aI, bI + bi);
                    }
#pragma unroll
                    for (int nt = 0; nt < 4; ++nt) {
                        const int bi = (nt >> 1) * 4 + (nt & 1) * 2;
                        mma16(accIm[mt][nt], aI, bR + bi);
                    }
#pragma unroll
                    for (int nt = 0; nt < 4; ++nt) {
                        const int bi = (nt >> 1) * 4 + (nt & 1) * 2;
                        mma16(accIm[mt][nt], aN, bI + bi);
                    }
                }
            }
            __syncthreads();
        }
    }

    // ---- epilogue ----
    const int r = lane >> 2;
    const int c = lane & 3;
    float* oRe = out + (size_t)b * D_DIM * D_DIM;
    float* oIm = oRe + (size_t)B_DIM * D_DIM * D_DIM;
#pragma unroll
    for (int mt = 0; mt < 2; ++mt) {
        const int d = dt * 128 + mr * 32 + mt * 16 + r;
#pragma unroll
        for (int nt = 0; nt < 4; ++nt) {
            const int e = et * 128 + nc * 32 + nt * 8 + 2 * c;
            *(float2*)(oRe + (size_t)d * D_DIM + e) =
                make_float2(accRe[mt][nt][0], accRe[mt][nt][1]);
            *(float2*)(oRe + (size_t)(d + 8) * D_DIM + e) =
                make_float2(accRe[mt][nt][2], accRe[mt][nt][3]);
            *(float2*)(oIm + (size_t)d * D_DIM + e) =
                make_float2(accIm[mt][nt][0], accIm[mt][nt][1]);
            *(float2*)(oIm + (size_t)(d + 8) * D_DIM + e) =
                make_float2(accIm[mt][nt][2], accIm[mt][nt][3]);
        }
    }
}

extern "C" void kernel_launch(void* const* d_in, const int* in_sizes, int n_in,
                              void* d_out, int out_size) {
    const int*   questions = (const int*)d_in[0];
    const float* qpos      = (const float*)d_in[1];
    const float* wemb      = (const float*)d_in[2];
    const float* cemb      = (const float*)d_in[3];
    const float* wq        = (const float*)d_in[4];
    float*       out       = (float*)d_out;

    cudaFuncSetAttribute(cmp_fp16d_kernel,
                         cudaFuncAttributeMaxDynamicSharedMemorySize, SMEM_BYTES);

    dim3 grid(2 /*e-half*/, 2 /*d-half*/, B_DIM);
    cmp_fp16d_kernel<<<grid, 512, SMEM_BYTES>>>(questions, qpos, wemb, cemb,
                                                wq, out);
}